// round 9
// baseline (speedup 1.0000x reference)
#include <cuda_runtime.h>
#include <cuda_bf16.h>
#include <math_constants.h>

// Two-level grid NN lookup + sigmoid(saliency).
// Radar binned on 16^3 grid (cell 6.25); queries binned on 8^3 grid (12.5).
// Query kernel: one block per 8^3 cell stages the 4x4x4 patch of 16^3 cells
// covering [block cell +- 6.25] (~78 pts) into smem; 2 threads per query
// scan it in lockstep (broadcast LDS), pair-merged via shfl.
// Tier-1 final if best < 38.0  (excluded true dist^2 > 39.0625, slack >= 1.0).
// Tier-2: 5x5x5 of 16^3 around the query's own cell; final if best < 155.25
//   (excluded > 156.25). Tier-3 / any bucket overflow: full brute-force scan.
// All reductions are u64 min over (ordered-dist | orig idx): order-invariant,
// ties -> smallest original index == jnp.argmin first occurrence. Output is
// provably identical to a full argmin regardless of which tier finishes.
// Distance arithmetic bit-identical to the reference:
//   l2/r2 : round(x*x)+round(y*y)+round(z*z), rounded adds (NO fma)
//   cross : fma chain (K=3 GEMM style);  dist : fmaf(-2,c, round(l2+r2))

#define RGDIM  16
#define RNCELL (RGDIM * RGDIM * RGDIM)     // 4096
#define RCELLW 6.25f
#define QGDIM  8
#define QNCELL (QGDIM * QGDIM * QGDIM)     // 512
#define QCELLW 12.5f
#define MAXNPT 8192
#define MAXV   65536
#define CAP_R  16
#define CAP_Q  256
#define SCAP   512
#define PB     256
#define QBLK   256

#define T1_KEY 0xC2180000u   /* ordered(38.0f)   */
#define T2_KEY 0xC31B4000u   /* ordered(155.25f) */

__device__ int    g_counts[RNCELL + QNCELL];  // [0,4096): radar16, rest: query8
__device__ float4 g_pts[MAXNPT];              // raw order {x,y,z,r2} (fallback)
__device__ float  g_sal[MAXNPT];
__device__ float4 g_rbucket[RNCELL * CAP_R];
__device__ int    g_rbidx[RNCELL * CAP_R];
__device__ int    g_qbucket[QNCELL * CAP_Q];
__device__ int    g_qcell[MAXV];

__device__ __forceinline__ float sum_sq_ref(float x, float y, float z) {
    float x2 = __fmul_rn(x, x);
    float y2 = __fmul_rn(y, y);
    float z2 = __fmul_rn(z, z);
    return __fadd_rn(__fadd_rn(x2, y2), z2);
}

__device__ __forceinline__ int ccoord16(float x) {
    int c = (int)(x * (1.0f / RCELLW));
    return min(max(c, 0), RGDIM - 1);
}
__device__ __forceinline__ int ccoord8(float x) {
    int c = (int)(x * (1.0f / QCELLW));
    return min(max(c, 0), QGDIM - 1);
}

__device__ __forceinline__ unsigned float_ordered(float f) {
    unsigned u = __float_as_uint(f);
    return (u & 0x80000000u) ? ~u : (u | 0x80000000u);
}

__device__ __forceinline__ unsigned long long dist_key(
    float x, float y, float z, float l2, float4 pt, int idx) {
    float c = fmaf(z, pt.z, fmaf(y, pt.y, __fmul_rn(x, pt.x)));
    float d = fmaf(-2.0f, c, __fadd_rn(l2, pt.w));
    return ((unsigned long long)float_ordered(d) << 32) | (unsigned)idx;
}

__global__ void prep_kernel(const float* __restrict__ feat,
                            const float* __restrict__ rcoords,
                            const float* __restrict__ lcoords,
                            int N, int V) {
    int t = blockIdx.x * blockDim.x + threadIdx.x;
    if (t < N) {
        int n = t;
        float rx = rcoords[3 * n + 0];
        float ry = rcoords[3 * n + 1];
        float rz = rcoords[3 * n + 2];
        float4 p = make_float4(rx, ry, rz, sum_sq_ref(rx, ry, rz));
        g_pts[n] = p;
        float f0 = feat[64 * n + 0];
        float f1 = feat[64 * n + 1];
        float s = __fadd_rn(__fmul_rn(0.6f, fabsf(f0)), __fmul_rn(0.4f, f1));
        g_sal[n] = 1.0f / (1.0f + expf(-s));
        int c = (ccoord16(rz) * RGDIM + ccoord16(ry)) * RGDIM + ccoord16(rx);
        int pos = atomicAdd(&g_counts[c], 1);
        if (pos < CAP_R) {
            g_rbucket[c * CAP_R + pos] = p;
            g_rbidx[c * CAP_R + pos] = n;
        }
    } else if (t < N + V) {
        int v = t - N;
        float x = lcoords[3 * v + 0];
        float y = lcoords[3 * v + 1];
        float z = lcoords[3 * v + 2];
        int c = (ccoord8(z) * QGDIM + ccoord8(y)) * QGDIM + ccoord8(x);
        g_qcell[v] = c;
        int pos = atomicAdd(&g_counts[RNCELL + c], 1);
        if (pos < CAP_Q) g_qbucket[c * CAP_Q + pos] = v;
    }
}

// Tier-2: 5x5x5 of 16^3 around the query's own cell, from global buckets.
__device__ unsigned long long tier2_scan(
    float x, float y, float z, float l2, int half,
    unsigned long long best, int* ovf) {
    int qcx = ccoord16(x), qcy = ccoord16(y), qcz = ccoord16(z);
    int x0 = max(qcx - 2, 0), x1 = min(qcx + 2, RGDIM - 1);
    int y0 = max(qcy - 2, 0), y1 = min(qcy + 2, RGDIM - 1);
    int z0 = max(qcz - 2, 0), z1 = min(qcz + 2, RGDIM - 1);
    int ci = 0;
    for (int dz = z0; dz <= z1; dz++)
        for (int dy = y0; dy <= y1; dy++)
            for (int dx = x0; dx <= x1; dx++) {
                if (((ci++) & 1) != half) continue;
                int c = (dz * RGDIM + dy) * RGDIM + dx;
                int cnt = g_counts[c];
                if (cnt > CAP_R) { *ovf = 1; cnt = CAP_R; }
                for (int i = 0; i < cnt; i++)
                    best = min(best, dist_key(x, y, z, l2,
                                              g_rbucket[c * CAP_R + i],
                                              g_rbidx[c * CAP_R + i]));
            }
    return best;
}

__global__ void __launch_bounds__(QBLK) query_kernel(
    const float* __restrict__ lcoords, float* __restrict__ out,
    int N, int V) {
    __shared__ float4 s_pts[SCAP];
    __shared__ int    s_idx[SCAP];
    __shared__ int    s_cnt[64];

    const int cell = blockIdx.x;
    const int qcnt = g_counts[RNCELL + cell];
    if (qcnt == 0) return;

    // 4x4x4 patch of 16^3 cells covering [block 12.5-cell +- 6.25], clamped.
    const int bz = cell >> 6, by = (cell >> 3) & 7, bx = cell & 7;
    const int x0 = max(2 * bx - 1, 0), x1 = min(2 * bx + 2, RGDIM - 1);
    const int y0 = max(2 * by - 1, 0), y1 = min(2 * by + 2, RGDIM - 1);
    const int z0 = max(2 * bz - 1, 0), z1 = min(2 * bz + 2, RGDIM - 1);
    const int nx = x1 - x0 + 1, ny = y1 - y0 + 1, nz = z1 - z0 + 1;
    const int ncells = nx * ny * nz;            // <= 64
    const int tid  = threadIdx.x;
    const int wid  = tid >> 5;
    const int lane = tid & 31;

    // Counts -> smem (linear order lx fastest, matching the staging loops).
    if (tid < ncells) {
        int lx = tid % nx, ly = (tid / nx) % ny, lz = tid / (nx * ny);
        int c = ((z0 + lz) * RGDIM + (y0 + ly)) * RGDIM + (x0 + lx);
        s_cnt[tid] = g_counts[c];
    }
    __syncthreads();

    // Stage buckets; cells round-robin over the 8 warps.
    bool ovf = false;
    int  dst = 0, ci = 0;
    for (int lz = 0; lz < nz; lz++)
        for (int ly = 0; ly < ny; ly++)
            for (int lx = 0; lx < nx; lx++) {
                int cnt = s_cnt[ci];
                ovf |= (cnt > CAP_R);
                cnt = min(cnt, CAP_R);
                if ((ci & 7) == wid && dst + cnt <= SCAP) {
                    int c = ((z0 + lz) * RGDIM + (y0 + ly)) * RGDIM + (x0 + lx);
                    for (int i = lane; i < cnt; i += 32) {
                        s_pts[dst + i] = g_rbucket[c * CAP_R + i];
                        s_idx[dst + i] = g_rbidx[c * CAP_R + i];
                    }
                }
                dst += cnt;
                ci++;
            }
    const int  total    = dst;
    const bool use_smem = !ovf && (total <= SCAP - 8);
    const int  padded   = (total + 7) & ~7;
    if (use_smem && tid < padded - total) {
        s_pts[total + tid] = make_float4(0.f, 0.f, 0.f, CUDART_INF_F);
        s_idx[total + tid] = 0;
    }
    __syncthreads();

    // 2 threads per query; halves take alternating groups of 4 candidates.
    const int      half  = tid & 1;
    const unsigned pmask = 3u << (lane & 30);   // this pair's lanes only
    const bool     q_ovf = (qcnt > CAP_Q);
    const int      qn    = q_ovf ? V : qcnt;
    for (int q = (tid >> 1); q < qn; q += (QBLK >> 1)) {
        int v;
        if (q_ovf) { v = q; if (g_qcell[v] != cell) continue; }
        else       { v = g_qbucket[cell * CAP_Q + q]; }

        const float x = lcoords[3 * v + 0];
        const float y = lcoords[3 * v + 1];
        const float z = lcoords[3 * v + 2];
        const float l2 = sum_sq_ref(x, y, z);

        unsigned long long best = ~0ull;
        if (use_smem) {
            unsigned long long b0 = ~0ull, b1 = ~0ull, b2 = ~0ull, b3 = ~0ull;
            for (int j = half * 4; j < padded; j += 8) {
                b0 = min(b0, dist_key(x, y, z, l2, s_pts[j + 0], s_idx[j + 0]));
                b1 = min(b1, dist_key(x, y, z, l2, s_pts[j + 1], s_idx[j + 1]));
                b2 = min(b2, dist_key(x, y, z, l2, s_pts[j + 2], s_idx[j + 2]));
                b3 = min(b3, dist_key(x, y, z, l2, s_pts[j + 3], s_idx[j + 3]));
            }
            best = min(min(b0, b1), min(b2, b3));
        }
        best = min(best, __shfl_xor_sync(pmask, best, 1));

        if (ovf) {
            for (int p = half; p < N; p += 2)
                best = min(best, dist_key(x, y, z, l2, g_pts[p], p));
            best = min(best, __shfl_xor_sync(pmask, best, 1));
        } else if ((unsigned)(best >> 32) >= T1_KEY) {
            int t2_ovf = 0;
            best = tier2_scan(x, y, z, l2, half, best, &t2_ovf);
            best = min(best, __shfl_xor_sync(pmask, best, 1));
            t2_ovf |= __shfl_xor_sync(pmask, t2_ovf, 1);
            if (t2_ovf || (unsigned)(best >> 32) >= T2_KEY) {
                for (int p = half; p < N; p += 2)
                    best = min(best, dist_key(x, y, z, l2, g_pts[p], p));
                best = min(best, __shfl_xor_sync(pmask, best, 1));
            }
        }

        if (half == 0)
            out[v] = g_sal[(unsigned)best];
    }
}

extern "C" void kernel_launch(void* const* d_in, const int* in_sizes, int n_in,
                              void* d_out, int out_size) {
    const float* feat    = (const float*)d_in[0];   // [N, 64]
    const float* lcoords = (const float*)d_in[1];   // [V, 3]
    const float* rcoords = (const float*)d_in[2];   // [N, 3]
    float* out = (float*)d_out;                     // [V]

    int N = in_sizes[0] / 64;
    int V = in_sizes[1] / 3;
    int NV = N + V;

    void* counts_ptr = nullptr;
    cudaGetSymbolAddress(&counts_ptr, g_counts);
    cudaMemsetAsync(counts_ptr, 0, (RNCELL + QNCELL) * sizeof(int), 0);

    prep_kernel<<<(NV + PB - 1) / PB, PB>>>(feat, rcoords, lcoords, N, V);
    query_kernel<<<QNCELL, QBLK>>>(lcoords, out, N, V);
}

// round 10
// speedup vs baseline: 1.5003x; 1.5003x over previous
#include <cuda_runtime.h>
#include <cuda_bf16.h>
#include <math_constants.h>

// Two-level grid NN + sigmoid(saliency). Radar on 16^3 (cell 6.25), queries
// on 8^3 (12.5). Query kernel: block per 8^3 cell stages the 4x4x4 patch of
// 16^3 buckets (slot-parallel, high MLP); 2 threads/query scan it in lockstep.
// Finality: unstaged points have true dist^2 > 39.0625, so best < 38.0
// (>=1.0 rounding slack) is final. Non-final queries (~0.6%) go to a smem
// list processed block-cooperatively: tier-2 = 5x5x5 of 16^3 around the
// query's own cell (excluded > 156.25 -> bound 155.25), else cooperative
// full scan. Any bucket overflow forces the cooperative fallback. All
// reductions are u64 min over (ordered-dist | orig idx): order-invariant,
// ties -> smallest original index == jnp.argmin first occurrence.
// Distance arithmetic bit-identical to the reference:
//   l2/r2 : round(x*x)+round(y*y)+round(z*z), rounded adds (NO fma)
//   cross : fma chain (K=3 GEMM style);  dist : fmaf(-2,c, round(l2+r2))

#define RGDIM  16
#define RNCELL (RGDIM * RGDIM * RGDIM)     // 4096
#define RCELLW 6.25f
#define QGDIM  8
#define QNCELL (QGDIM * QGDIM * QGDIM)     // 512
#define QCELLW 12.5f
#define MAXNPT 8192
#define MAXV   65536
#define CAP_R  16
#define CAP_Q  256
#define SCAP   1040
#define PB     256
#define QBLK   256

#define T1_KEY 0xC2180000u   /* ordered(38.0f)   */
#define T2_KEY 0xC31B4000u   /* ordered(155.25f) */

__device__ int    g_counts[RNCELL + QNCELL];
__device__ float4 g_pts[MAXNPT];              // raw order {x,y,z,r2}
__device__ float  g_sal[MAXNPT];
__device__ float4 g_rbucket[RNCELL * CAP_R];
__device__ int    g_rbidx[RNCELL * CAP_R];
__device__ int    g_qbucket[QNCELL * CAP_Q];
__device__ int    g_qcell[MAXV];

__device__ __forceinline__ float sum_sq_ref(float x, float y, float z) {
    float x2 = __fmul_rn(x, x);
    float y2 = __fmul_rn(y, y);
    float z2 = __fmul_rn(z, z);
    return __fadd_rn(__fadd_rn(x2, y2), z2);
}

__device__ __forceinline__ int ccoord16(float x) {
    int c = (int)(x * (1.0f / RCELLW));
    return min(max(c, 0), RGDIM - 1);
}
__device__ __forceinline__ int ccoord8(float x) {
    int c = (int)(x * (1.0f / QCELLW));
    return min(max(c, 0), QGDIM - 1);
}

__device__ __forceinline__ unsigned float_ordered(float f) {
    unsigned u = __float_as_uint(f);
    return (u & 0x80000000u) ? ~u : (u | 0x80000000u);
}

__device__ __forceinline__ unsigned long long dist_key(
    float x, float y, float z, float l2, float4 pt, int idx) {
    float c = fmaf(z, pt.z, fmaf(y, pt.y, __fmul_rn(x, pt.x)));
    float d = fmaf(-2.0f, c, __fadd_rn(l2, pt.w));
    return ((unsigned long long)float_ordered(d) << 32) | (unsigned)idx;
}

__global__ void prep_kernel(const float* __restrict__ feat,
                            const float* __restrict__ rcoords,
                            const float* __restrict__ lcoords,
                            int N, int V) {
    int t = blockIdx.x * blockDim.x + threadIdx.x;
    if (t < N) {
        int n = t;
        float rx = rcoords[3 * n + 0];
        float ry = rcoords[3 * n + 1];
        float rz = rcoords[3 * n + 2];
        float4 p = make_float4(rx, ry, rz, sum_sq_ref(rx, ry, rz));
        g_pts[n] = p;
        float f0 = feat[64 * n + 0];
        float f1 = feat[64 * n + 1];
        float s = __fadd_rn(__fmul_rn(0.6f, fabsf(f0)), __fmul_rn(0.4f, f1));
        g_sal[n] = 1.0f / (1.0f + expf(-s));
        int c = (ccoord16(rz) * RGDIM + ccoord16(ry)) * RGDIM + ccoord16(rx);
        int pos = atomicAdd(&g_counts[c], 1);
        if (pos < CAP_R) {
            g_rbucket[c * CAP_R + pos] = p;
            g_rbidx[c * CAP_R + pos] = n;
        }
    } else if (t < N + V) {
        int v = t - N;
        float x = lcoords[3 * v + 0];
        float y = lcoords[3 * v + 1];
        float z = lcoords[3 * v + 2];
        int c = (ccoord8(z) * QGDIM + ccoord8(y)) * QGDIM + ccoord8(x);
        g_qcell[v] = c;
        int pos = atomicAdd(&g_counts[RNCELL + c], 1);
        if (pos < CAP_Q) g_qbucket[c * CAP_Q + pos] = v;
    }
}

// Block-wide u64-min. All QBLK threads must participate. Two syncthreads.
__device__ __forceinline__ unsigned long long block_min_u64(
    unsigned long long v, unsigned long long* s_red, int wid, int lane) {
    #pragma unroll
    for (int s = 16; s; s >>= 1)
        v = min(v, __shfl_xor_sync(0xffffffffu, v, s));
    if (lane == 0) s_red[wid] = v;
    __syncthreads();
    if (wid == 0) {
        unsigned long long w = (lane < QBLK / 32) ? s_red[lane] : ~0ull;
        #pragma unroll
        for (int s = 4; s; s >>= 1)
            w = min(w, __shfl_xor_sync(0xffffffffu, w, s));
        if (lane == 0) s_red[8] = w;
    }
    __syncthreads();
    return s_red[8];
}

__global__ void __launch_bounds__(QBLK) query_kernel(
    const float* __restrict__ lcoords, float* __restrict__ out,
    int N, int V) {
    __shared__ float4 s_pts[SCAP];
    __shared__ int    s_idx[SCAP];
    __shared__ int    s_cnt[64];
    __shared__ int    s_off[64];
    __shared__ int    s_total;
    __shared__ int    s_t2n;
    __shared__ int    s_t2v[CAP_Q];
    __shared__ unsigned long long s_t2k[CAP_Q];
    __shared__ unsigned long long s_red[9];

    const int cell = blockIdx.x;
    const int qcnt = g_counts[RNCELL + cell];
    if (qcnt == 0) return;

    const int bz = cell >> 6, by = (cell >> 3) & 7, bx = cell & 7;
    const int x0 = max(2 * bx - 1, 0), x1 = min(2 * bx + 2, RGDIM - 1);
    const int y0 = max(2 * by - 1, 0), y1 = min(2 * by + 2, RGDIM - 1);
    const int z0 = max(2 * bz - 1, 0), z1 = min(2 * bz + 2, RGDIM - 1);
    const int nx = x1 - x0 + 1, ny = y1 - y0 + 1, nz = z1 - z0 + 1;
    const int ncells = nx * ny * nz;              // <= 64
    const int tid  = threadIdx.x;
    const int wid  = tid >> 5;
    const int lane = tid & 31;

    if (tid == 0) s_t2n = 0;
    int rawcnt = 0;
    if (tid < ncells) {
        int lx = tid % nx, ly = (tid / nx) % ny, lz = tid / (nx * ny);
        int c = ((z0 + lz) * RGDIM + (y0 + ly)) * RGDIM + (x0 + lx);
        rawcnt = g_counts[c];
        s_cnt[tid] = min(rawcnt, CAP_R);
    }
    const int r_ovf = __syncthreads_or(rawcnt > CAP_R);

    // Per-cell exclusive offsets (parallel partial sums; ncells <= 64).
    if (tid < ncells) {
        int off = 0;
        for (int i = 0; i < tid; i++) off += s_cnt[i];
        s_off[tid] = off;
        if (tid == ncells - 1) s_total = off + s_cnt[tid];
    }
    __syncthreads();
    const int total = s_total;

    // Slot-parallel staging: thread handles (cell slot/16, entry slot%16).
    for (int slot = tid; slot < ncells * CAP_R; slot += QBLK) {
        int ci = slot >> 4, i = slot & (CAP_R - 1);
        if (i < s_cnt[ci]) {
            int lx = ci % nx, ly = (ci / nx) % ny, lz = ci / (nx * ny);
            int c = ((z0 + lz) * RGDIM + (y0 + ly)) * RGDIM + (x0 + lx);
            s_pts[s_off[ci] + i] = g_rbucket[c * CAP_R + i];
            s_idx[s_off[ci] + i] = g_rbidx[c * CAP_R + i];
        }
    }
    const int padded = (total + 7) & ~7;
    if (tid < padded - total) {
        s_pts[total + tid] = make_float4(0.f, 0.f, 0.f, CUDART_INF_F);
        s_idx[total + tid] = 0;
    }
    __syncthreads();

    const bool q_ovf = (qcnt > CAP_Q);
    if (!q_ovf) {
        // 2 threads per query; halves take alternating groups of 4.
        const int      half  = tid & 1;
        const unsigned pmask = 3u << (lane & 30);
        for (int q = (tid >> 1); q < qcnt; q += (QBLK >> 1)) {
            const int v = g_qbucket[cell * CAP_Q + q];
            const float x = lcoords[3 * v + 0];
            const float y = lcoords[3 * v + 1];
            const float z = lcoords[3 * v + 2];
            const float l2 = sum_sq_ref(x, y, z);

            unsigned long long b0 = ~0ull, b1 = ~0ull, b2 = ~0ull, b3 = ~0ull;
            for (int j = half * 4; j < padded; j += 8) {
                b0 = min(b0, dist_key(x, y, z, l2, s_pts[j + 0], s_idx[j + 0]));
                b1 = min(b1, dist_key(x, y, z, l2, s_pts[j + 1], s_idx[j + 1]));
                b2 = min(b2, dist_key(x, y, z, l2, s_pts[j + 2], s_idx[j + 2]));
                b3 = min(b3, dist_key(x, y, z, l2, s_pts[j + 3], s_idx[j + 3]));
            }
            unsigned long long best = min(min(b0, b1), min(b2, b3));
            best = min(best, __shfl_xor_sync(pmask, best, 1));

            if (r_ovf || (unsigned)(best >> 32) >= T1_KEY) {
                if (half == 0) {
                    int k = atomicAdd(&s_t2n, 1);   // k < qcnt <= CAP_Q
                    s_t2v[k] = v;
                    s_t2k[k] = best;
                }
            } else if (half == 0) {
                out[v] = g_sal[(unsigned)best];
            }
        }
    }
    __syncthreads();

    // Block-cooperative fallback for listed queries (~0.6 per block).
    const int nt2 = s_t2n;
    for (int k = 0; k < nt2; k++) {
        const int v = s_t2v[k];
        const float x = lcoords[3 * v + 0];
        const float y = lcoords[3 * v + 1];
        const float z = lcoords[3 * v + 2];
        const float l2 = sum_sq_ref(x, y, z);
        unsigned long long best = s_t2k[k];

        int need_full = r_ovf;
        if (!r_ovf) {
            // Tier-2: 5x5x5 of 16^3 around the query's own cell, one cell
            // per thread (<=125 active), fully parallel LDGs.
            int qcx = ccoord16(x), qcy = ccoord16(y), qcz = ccoord16(z);
            int tx0 = max(qcx - 2, 0), tx1 = min(qcx + 2, RGDIM - 1);
            int ty0 = max(qcy - 2, 0), ty1 = min(qcy + 2, RGDIM - 1);
            int tz0 = max(qcz - 2, 0), tz1 = min(qcz + 2, RGDIM - 1);
            int tnx = tx1 - tx0 + 1, tny = ty1 - ty0 + 1, tnz = tz1 - tz0 + 1;
            int tn = tnx * tny * tnz;
            unsigned long long mine = ~0ull;
            int t2raw = 0;
            if (tid < tn) {
                int lx = tid % tnx, ly = (tid / tnx) % tny, lz = tid / (tnx * tny);
                int c = ((tz0 + lz) * RGDIM + (ty0 + ly)) * RGDIM + (tx0 + lx);
                t2raw = g_counts[c];
                int cnt = min(t2raw, CAP_R);
                for (int i = 0; i < cnt; i++)
                    mine = min(mine, dist_key(x, y, z, l2,
                                              g_rbucket[c * CAP_R + i],
                                              g_rbidx[c * CAP_R + i]));
            }
            int t2_ovf = __syncthreads_or(t2raw > CAP_R);
            best = min(best, block_min_u64(mine, s_red, wid, lane));
            need_full = t2_ovf || ((unsigned)(best >> 32) >= T2_KEY);
        }
        if (need_full) {
            unsigned long long mine = ~0ull;
            for (int p = tid; p < N; p += QBLK)
                mine = min(mine, dist_key(x, y, z, l2, g_pts[p], p));
            best = min(best, block_min_u64(mine, s_red, wid, lane));
        }
        if (tid == 0) out[v] = g_sal[(unsigned)best];
        __syncthreads();
    }

    if (q_ovf) {
        // Astronomically rare (qcnt > CAP_Q): cooperative full scan per member.
        for (int v = 0; v < V; v++) {
            if (g_qcell[v] != cell) continue;
            const float x = lcoords[3 * v + 0];
            const float y = lcoords[3 * v + 1];
            const float z = lcoords[3 * v + 2];
            const float l2 = sum_sq_ref(x, y, z);
            unsigned long long mine = ~0ull;
            for (int p = tid; p < N; p += QBLK)
                mine = min(mine, dist_key(x, y, z, l2, g_pts[p], p));
            unsigned long long best = block_min_u64(mine, s_red, wid, lane);
            if (tid == 0) out[v] = g_sal[(unsigned)best];
            __syncthreads();
        }
    }
}

extern "C" void kernel_launch(void* const* d_in, const int* in_sizes, int n_in,
                              void* d_out, int out_size) {
    const float* feat    = (const float*)d_in[0];   // [N, 64]
    const float* lcoords = (const float*)d_in[1];   // [V, 3]
    const float* rcoords = (const float*)d_in[2];   // [N, 3]
    float* out = (float*)d_out;                     // [V]

    int N = in_sizes[0] / 64;
    int V = in_sizes[1] / 3;
    int NV = N + V;

    void* counts_ptr = nullptr;
    cudaGetSymbolAddress(&counts_ptr, g_counts);
    cudaMemsetAsync(counts_ptr, 0, (RNCELL + QNCELL) * sizeof(int), 0);

    prep_kernel<<<(NV + PB - 1) / PB, PB>>>(feat, rcoords, lcoords, N, V);
    query_kernel<<<QNCELL, QBLK>>>(lcoords, out, N, V);
}

// round 11
// speedup vs baseline: 2.9116x; 1.9407x over previous
#include <cuda_runtime.h>
#include <cuda_bf16.h>
#include <math_constants.h>

// Two-level grid NN + sigmoid(saliency). Radar binned on 16^3 (cell 6.25),
// queries on 8^3 (12.5). Query kernel: block per 8^3 cell stages the 6x6x6
// patch of 16^3 buckets (covers block +- 12.5) into smem, ordered so the
// inner 4x4x4 (covers block +- 6.25, ~78 pts) comes first.
// Main loop (2 thr/query) scans ONLY the inner region; unscanned points have
// true dist^2 > 39.0625, so best < 38.0 (>=1.0 rounding slack) is final.
// Non-final queries (~0.6%) go to a smem list; epilogue: one warp per listed
// query scans the whole staged patch lane-parallel (unstaged > 156.25 ->
// bound 155.25), else warp full-scans all N. Any overflow -> full-scan path.
// All reductions are u64 min over (ordered-dist | orig idx): order-invariant,
// ties -> smallest original index == jnp.argmin first occurrence.
// Distance arithmetic bit-identical to the reference:
//   l2/r2 : round(x*x)+round(y*y)+round(z*z), rounded adds (NO fma)
//   cross : fma chain (K=3 GEMM style);  dist : fmaf(-2,c, round(l2+r2))

#define RGDIM  16
#define RNCELL (RGDIM * RGDIM * RGDIM)     // 4096
#define RCELLW 6.25f
#define QGDIM  8
#define QNCELL (QGDIM * QGDIM * QGDIM)     // 512
#define QCELLW 12.5f
#define MAXNPT 8192
#define MAXV   65536
#define CAP_R  16
#define CAP_Q  224
#define SCAP   528
#define NPATCH 216                         // 6x6x6
#define PB     256
#define QBLK   256

#define T1_KEY 0xC2180000u   /* ordered(38.0f)   */
#define T2_KEY 0xC31B4000u   /* ordered(155.25f) */

__device__ int    g_counts[RNCELL + QNCELL];
__device__ float4 g_pts[MAXNPT];              // raw order {x,y,z,r2}
__device__ float  g_sal[MAXNPT];
__device__ float4 g_rbucket[RNCELL * CAP_R];
__device__ int    g_rbidx[RNCELL * CAP_R];
__device__ int    g_qbucket[QNCELL * CAP_Q];
__device__ int    g_qcell[MAXV];

__device__ __forceinline__ float sum_sq_ref(float x, float y, float z) {
    float x2 = __fmul_rn(x, x);
    float y2 = __fmul_rn(y, y);
    float z2 = __fmul_rn(z, z);
    return __fadd_rn(__fadd_rn(x2, y2), z2);
}

__device__ __forceinline__ int ccoord16(float x) {
    int c = (int)(x * (1.0f / RCELLW));
    return min(max(c, 0), RGDIM - 1);
}
__device__ __forceinline__ int ccoord8(float x) {
    int c = (int)(x * (1.0f / QCELLW));
    return min(max(c, 0), QGDIM - 1);
}

__device__ __forceinline__ unsigned float_ordered(float f) {
    unsigned u = __float_as_uint(f);
    return (u & 0x80000000u) ? ~u : (u | 0x80000000u);
}

__device__ __forceinline__ unsigned long long dist_key(
    float x, float y, float z, float l2, float4 pt, int idx) {
    float c = fmaf(z, pt.z, fmaf(y, pt.y, __fmul_rn(x, pt.x)));
    float d = fmaf(-2.0f, c, __fadd_rn(l2, pt.w));
    return ((unsigned long long)float_ordered(d) << 32) | (unsigned)idx;
}

__global__ void prep_kernel(const float* __restrict__ feat,
                            const float* __restrict__ rcoords,
                            const float* __restrict__ lcoords,
                            int N, int V) {
    int t = blockIdx.x * blockDim.x + threadIdx.x;
    if (t < N) {
        int n = t;
        float rx = rcoords[3 * n + 0];
        float ry = rcoords[3 * n + 1];
        float rz = rcoords[3 * n + 2];
        float4 p = make_float4(rx, ry, rz, sum_sq_ref(rx, ry, rz));
        g_pts[n] = p;
        float f0 = feat[64 * n + 0];
        float f1 = feat[64 * n + 1];
        float s = __fadd_rn(__fmul_rn(0.6f, fabsf(f0)), __fmul_rn(0.4f, f1));
        g_sal[n] = 1.0f / (1.0f + expf(-s));
        int c = (ccoord16(rz) * RGDIM + ccoord16(ry)) * RGDIM + ccoord16(rx);
        int pos = atomicAdd(&g_counts[c], 1);
        if (pos < CAP_R) {
            g_rbucket[c * CAP_R + pos] = p;
            g_rbidx[c * CAP_R + pos] = n;
        }
    } else if (t < N + V) {
        int v = t - N;
        float x = lcoords[3 * v + 0];
        float y = lcoords[3 * v + 1];
        float z = lcoords[3 * v + 2];
        int c = (ccoord8(z) * QGDIM + ccoord8(y)) * QGDIM + ccoord8(x);
        g_qcell[v] = c;
        int pos = atomicAdd(&g_counts[RNCELL + c], 1);
        if (pos < CAP_Q) g_qbucket[c * CAP_Q + pos] = v;
    }
}

// n1(c) = #{u < c : u in [1,4]}
__device__ __forceinline__ int n1f(int c) { return min(max(c - 1, 0), 4); }

__global__ void __launch_bounds__(QBLK) query_kernel(
    const float* __restrict__ lcoords, float* __restrict__ out,
    int N, int V) {
    __shared__ float4 s_pts[SCAP];
    __shared__ int    s_idx[SCAP];
    __shared__ int    s_cnt[QBLK];     // per-rank capped count (pad 0)
    __shared__ int    s_off[QBLK];     // per-rank exclusive offset
    __shared__ int    s_cid[NPATCH];   // per-rank absolute cell id (-1 invalid)
    __shared__ int    s_scan[QBLK];    // Hillis-Steele workspace
    __shared__ int    s_innerTot, s_total, s_ln;
    __shared__ int    s_lv[CAP_Q];
    __shared__ unsigned long long s_lk[CAP_Q];

    const int cell = blockIdx.x;
    const int qcnt = g_counts[RNCELL + cell];
    if (qcnt == 0) return;

    const int bz = cell >> 6, by = (cell >> 3) & 7, bx = cell & 7;
    const int tid  = threadIdx.x;
    const int wid  = tid >> 5;
    const int lane = tid & 31;

    // ---- Per-cell rank, id, count (inner 4x4x4 gets ranks 0..63) ----
    int rawcnt = 0;
    if (tid < NPATCH) {
        int ox = tid % 6, oy = (tid / 6) % 6, oz = tid / 36;
        int ax = 2 * bx - 2 + ox, ay = 2 * by - 2 + oy, az = 2 * bz - 2 + oz;
        bool inX = (ox >= 1 && ox <= 4), inY = (oy >= 1 && oy <= 4),
             inZ = (oz >= 1 && oz <= 4);
        int innerBefore = n1f(oz) * 16 + (inZ ? (n1f(oy) * 4 + (inY ? n1f(ox) : 0)) : 0);
        int rank = (inX && inY && inZ) ? innerBefore : 64 + (tid - innerBefore);
        int cid = -1;
        if ((unsigned)ax < RGDIM && (unsigned)ay < RGDIM && (unsigned)az < RGDIM) {
            cid = (az * RGDIM + ay) * RGDIM + ax;
            rawcnt = g_counts[cid];
        }
        s_cid[rank]  = cid;
        s_cnt[rank]  = min(rawcnt, CAP_R);
        s_scan[rank] = min(rawcnt, CAP_R);
    } else {
        s_cnt[tid]  = 0;
        s_scan[tid] = 0;
    }
    if (tid == 0) s_ln = 0;
    const int r_ovf = __syncthreads_or(rawcnt > CAP_R);

    // ---- Inclusive scan over 256 entries ----
    #pragma unroll
    for (int off = 1; off < QBLK; off <<= 1) {
        int u = (tid >= off) ? s_scan[tid - off] : 0;
        __syncthreads();
        s_scan[tid] += u;
        __syncthreads();
    }
    s_off[tid] = s_scan[tid] - s_cnt[tid];
    if (tid == 63)       s_innerTot = s_scan[63];
    if (tid == QBLK - 1) s_total    = s_scan[QBLK - 1];
    __syncthreads();

    const int  total    = s_total;
    const int  innerTot = s_innerTot;
    const bool big_ovf  = r_ovf || (total > SCAP - 8);

    // ---- Slot-parallel staging (full MLP) ----
    if (!big_ovf) {
        for (int slot = tid; slot < NPATCH * CAP_R; slot += QBLK) {
            int ci = slot >> 4, i = slot & (CAP_R - 1);
            if (i < s_cnt[ci]) {
                int c = s_cid[ci];
                int d = s_off[ci] + i;
                s_pts[d] = g_rbucket[c * CAP_R + i];
                s_idx[d] = g_rbidx[c * CAP_R + i];
            }
        }
        int paddedTotal = (total + 7) & ~7;
        if (tid < paddedTotal - total) {
            s_pts[total + tid] = make_float4(0.f, 0.f, 0.f, CUDART_INF_F);
            s_idx[total + tid] = 0;
        }
    }
    __syncthreads();

    const int paddedTotal = (total + 7) & ~7;
    const int t1end = min((innerTot + 7) & ~7, paddedTotal);

    // ---- Main loop: 2 threads/query, inner region only ----
    const bool q_ovf = (qcnt > CAP_Q);
    if (!q_ovf) {
        const int      half  = tid & 1;
        const unsigned pmask = 3u << (lane & 30);
        for (int q = (tid >> 1); q < qcnt; q += (QBLK >> 1)) {
            const int v = g_qbucket[cell * CAP_Q + q];
            const float x = lcoords[3 * v + 0];
            const float y = lcoords[3 * v + 1];
            const float z = lcoords[3 * v + 2];
            const float l2 = sum_sq_ref(x, y, z);

            unsigned long long best = ~0ull;
            if (!big_ovf) {
                unsigned long long b0 = ~0ull, b1 = ~0ull, b2 = ~0ull, b3 = ~0ull;
                for (int j = half * 4; j < t1end; j += 8) {
                    b0 = min(b0, dist_key(x, y, z, l2, s_pts[j + 0], s_idx[j + 0]));
                    b1 = min(b1, dist_key(x, y, z, l2, s_pts[j + 1], s_idx[j + 1]));
                    b2 = min(b2, dist_key(x, y, z, l2, s_pts[j + 2], s_idx[j + 2]));
                    b3 = min(b3, dist_key(x, y, z, l2, s_pts[j + 3], s_idx[j + 3]));
                }
                best = min(min(b0, b1), min(b2, b3));
                best = min(best, __shfl_xor_sync(pmask, best, 1));
            }

            if (big_ovf || (unsigned)(best >> 32) >= T1_KEY) {
                if (half == 0) {
                    int k = atomicAdd(&s_ln, 1);    // k < qcnt <= CAP_Q
                    s_lv[k] = v;
                    s_lk[k] = best;
                }
            } else if (half == 0) {
                out[v] = g_sal[(unsigned)best];
            }
        }
    }
    __syncthreads();

    // ---- Warp-autonomous epilogue for listed queries (~0.6 per block) ----
    const int ln = s_ln;
    for (int k = wid; k < ln; k += QBLK / 32) {
        const int v = s_lv[k];
        const float x = lcoords[3 * v + 0];
        const float y = lcoords[3 * v + 1];
        const float z = lcoords[3 * v + 2];
        const float l2 = sum_sq_ref(x, y, z);
        unsigned long long best = s_lk[k];

        if (!big_ovf) {
            unsigned long long mine = ~0ull;
            for (int j = lane; j < total; j += 32)
                mine = min(mine, dist_key(x, y, z, l2, s_pts[j], s_idx[j]));
            #pragma unroll
            for (int s = 16; s; s >>= 1)
                mine = min(mine, __shfl_xor_sync(0xffffffffu, mine, s));
            best = min(best, mine);
        }
        if (big_ovf || (unsigned)(best >> 32) >= T2_KEY) {
            unsigned long long mine = ~0ull;
            for (int p = lane; p < N; p += 32)
                mine = min(mine, dist_key(x, y, z, l2, g_pts[p], p));
            #pragma unroll
            for (int s = 16; s; s >>= 1)
                mine = min(mine, __shfl_xor_sync(0xffffffffu, mine, s));
            best = min(best, mine);
        }
        if (lane == 0) out[v] = g_sal[(unsigned)best];
    }

    // ---- Astronomically rare: query bucket overflow -> warp full scans ----
    if (q_ovf) {
        for (int v = wid; v < V; v += QBLK / 32) {
            if (g_qcell[v] != cell) continue;
            const float x = lcoords[3 * v + 0];
            const float y = lcoords[3 * v + 1];
            const float z = lcoords[3 * v + 2];
            const float l2 = sum_sq_ref(x, y, z);
            unsigned long long mine = ~0ull;
            for (int p = lane; p < N; p += 32)
                mine = min(mine, dist_key(x, y, z, l2, g_pts[p], p));
            #pragma unroll
            for (int s = 16; s; s >>= 1)
                mine = min(mine, __shfl_xor_sync(0xffffffffu, mine, s));
            if (lane == 0) out[v] = g_sal[(unsigned)mine];
        }
    }
}

extern "C" void kernel_launch(void* const* d_in, const int* in_sizes, int n_in,
                              void* d_out, int out_size) {
    const float* feat    = (const float*)d_in[0];   // [N, 64]
    const float* lcoords = (const float*)d_in[1];   // [V, 3]
    const float* rcoords = (const float*)d_in[2];   // [N, 3]
    float* out = (float*)d_out;                     // [V]

    int N = in_sizes[0] / 64;
    int V = in_sizes[1] / 3;
    int NV = N + V;

    void* counts_ptr = nullptr;
    cudaGetSymbolAddress(&counts_ptr, g_counts);
    cudaMemsetAsync(counts_ptr, 0, (RNCELL + QNCELL) * sizeof(int), 0);

    prep_kernel<<<(NV + PB - 1) / PB, PB>>>(feat, rcoords, lcoords, N, V);
    query_kernel<<<QNCELL, QBLK>>>(lcoords, out, N, V);
}